// round 7
// baseline (speedup 1.0000x reference)
#include <cuda_runtime.h>
#include <cstdint>

#define N_NODES 50000
#define NNZ_C   800000
#define N_ADJ   6
#define K_DIM   256
#define H_DIM   128
#define LN_EPS  1e-5f

// ---------------------------------------------------------------------------
// Device-global scratch
// ---------------------------------------------------------------------------
__device__ float g_h[(size_t)N_NODES * H_DIM];            // s0 = x@W+b
__device__ float g_acc[3][(size_t)N_NODES * H_DIM];       // s1, s2, s3 (RED targets)
__device__ int2  g_ecv[N_ADJ][NNZ_C];                     // zipped (col, val bits)

__device__ __forceinline__ float* state_ptr(int id) {
    return (id == 0) ? g_h : g_acc[id - 1];
}

// ---------------------------------------------------------------------------
// Zero the accumulators (RED targets) each call
// ---------------------------------------------------------------------------
__global__ void zero_kernel() {
    const size_t n4 = (size_t)3 * N_NODES * H_DIM / 4;
    float4* p = reinterpret_cast<float4*>(&g_acc[0][0]);
    const float4 z = make_float4(0.f, 0.f, 0.f, 0.f);
    for (size_t i = (size_t)blockIdx.x * blockDim.x + threadIdx.x; i < n4;
         i += (size_t)gridDim.x * blockDim.x)
        p[i] = z;
}

// ---------------------------------------------------------------------------
// Zip cols+vals into int2 (streaming, no reordering)
// ---------------------------------------------------------------------------
__global__ __launch_bounds__(256) void zip_kernel(const int*   __restrict__ cols_base,
                                                  const float* __restrict__ vals_base) {
    const size_t i = (size_t)blockIdx.x * blockDim.x + threadIdx.x;
    if (i < (size_t)N_ADJ * NNZ_C)
        (&g_ecv[0][0])[i] = make_int2(__ldg(cols_base + i),
                                      __float_as_int(__ldg(vals_base + i)));
}

// ---------------------------------------------------------------------------
// GEMM: g_h = X[50000,256] @ W[256,128] + b   (128x128 tile, 8x8/thread)
// ---------------------------------------------------------------------------
__global__ __launch_bounds__(256) void gemm_kernel(const float* __restrict__ X,
                                                   const float* __restrict__ W,
                                                   const float* __restrict__ bias) {
    __shared__ float As[8][128];
    __shared__ float Bs[8][128];

    const int tid = threadIdx.x;
    const int tx = tid & 15;
    const int ty = tid >> 4;
    const int row0 = blockIdx.x * 128;

    const int arow = tid >> 1;
    const int ak   = (tid & 1) * 4;
    const int grow = min(row0 + arow, N_NODES - 1);
    const int brow = tid >> 5;
    const int bcol = (tid & 31) * 4;

    float acc[8][8];
#pragma unroll
    for (int i = 0; i < 8; i++)
#pragma unroll
        for (int j = 0; j < 8; j++) acc[i][j] = 0.f;

    for (int k0 = 0; k0 < K_DIM; k0 += 8) {
        const float4 av = *reinterpret_cast<const float4*>(
            X + (size_t)grow * K_DIM + k0 + ak);
        const float4 bv = *reinterpret_cast<const float4*>(
            W + (size_t)(k0 + brow) * H_DIM + bcol);
        __syncthreads();
        As[ak + 0][arow] = av.x;
        As[ak + 1][arow] = av.y;
        As[ak + 2][arow] = av.z;
        As[ak + 3][arow] = av.w;
        *reinterpret_cast<float4*>(&Bs[brow][bcol]) = bv;
        __syncthreads();

#pragma unroll
        for (int kk = 0; kk < 8; kk++) {
            float a[8], b[8];
            const float4 a0 = *reinterpret_cast<const float4*>(&As[kk][ty * 8]);
            const float4 a1 = *reinterpret_cast<const float4*>(&As[kk][ty * 8 + 4]);
            const float4 b0 = *reinterpret_cast<const float4*>(&Bs[kk][tx * 8]);
            const float4 b1 = *reinterpret_cast<const float4*>(&Bs[kk][tx * 8 + 4]);
            a[0]=a0.x; a[1]=a0.y; a[2]=a0.z; a[3]=a0.w;
            a[4]=a1.x; a[5]=a1.y; a[6]=a1.z; a[7]=a1.w;
            b[0]=b0.x; b[1]=b0.y; b[2]=b0.z; b[3]=b0.w;
            b[4]=b1.x; b[5]=b1.y; b[6]=b1.z; b[7]=b1.w;
#pragma unroll
            for (int i = 0; i < 8; i++)
#pragma unroll
                for (int j = 0; j < 8; j++) acc[i][j] += a[i] * b[j];
        }
    }

    const int colb = tx * 8;
    const float4 bia0 = *reinterpret_cast<const float4*>(bias + colb);
    const float4 bia1 = *reinterpret_cast<const float4*>(bias + colb + 4);
#pragma unroll
    for (int i = 0; i < 8; i++) {
        const int row = row0 + ty * 8 + i;
        if (row < N_NODES) {
            float4 o0, o1;
            o0.x = acc[i][0] + bia0.x; o0.y = acc[i][1] + bia0.y;
            o0.z = acc[i][2] + bia0.z; o0.w = acc[i][3] + bia0.w;
            o1.x = acc[i][4] + bia1.x; o1.y = acc[i][5] + bia1.y;
            o1.z = acc[i][6] + bia1.z; o1.w = acc[i][7] + bia1.w;
            float* op = g_h + (size_t)row * H_DIM + colb;
            *reinterpret_cast<float4*>(op)     = o0;
            *reinterpret_cast<float4*>(op + 4) = o1;
        }
    }
}

// ---------------------------------------------------------------------------
// SpMM (COO + RED): one warp per 32-edge chunk, lane-cooperative metadata,
// explicit 4-deep gather batching so 4 independent LDG.128s are in flight
// before any RED is issued (REDs have no return -> batches also overlap).
// ---------------------------------------------------------------------------
__global__ __launch_bounds__(256) void spmm_kernel(const int* __restrict__ rows_base,
                                                   const int* __restrict__ idxp,
                                                   int src_id, int dst_id) {
    const int lane  = threadIdx.x & 31;
    const int chunk = (blockIdx.x * blockDim.x + threadIdx.x) >> 5;
    if (chunk >= NNZ_C / 32) return;

    const int a = __ldg(idxp);
    const float* __restrict__ src = state_ptr(src_id);
    float*       __restrict__ dst = state_ptr(dst_id);

    const size_t e0 = (size_t)chunk * 32;
    const int  myrow = __ldg(rows_base + (size_t)a * NNZ_C + e0 + lane);
    const int2 mycv  = __ldg(&g_ecv[a][e0 + lane]);

#pragma unroll
    for (int j = 0; j < 32; j += 4) {
        const int r0 = __shfl_sync(0xFFFFFFFFu, myrow, j + 0);
        const int r1 = __shfl_sync(0xFFFFFFFFu, myrow, j + 1);
        const int r2 = __shfl_sync(0xFFFFFFFFu, myrow, j + 2);
        const int r3 = __shfl_sync(0xFFFFFFFFu, myrow, j + 3);
        const int c0 = __shfl_sync(0xFFFFFFFFu, mycv.x, j + 0);
        const int c1 = __shfl_sync(0xFFFFFFFFu, mycv.x, j + 1);
        const int c2 = __shfl_sync(0xFFFFFFFFu, mycv.x, j + 2);
        const int c3 = __shfl_sync(0xFFFFFFFFu, mycv.x, j + 3);
        const float v0 = __int_as_float(__shfl_sync(0xFFFFFFFFu, mycv.y, j + 0));
        const float v1 = __int_as_float(__shfl_sync(0xFFFFFFFFu, mycv.y, j + 1));
        const float v2 = __int_as_float(__shfl_sync(0xFFFFFFFFu, mycv.y, j + 2));
        const float v3 = __int_as_float(__shfl_sync(0xFFFFFFFFu, mycv.y, j + 3));

        // 4 independent gathers in flight
        const float4 x0 = __ldg(reinterpret_cast<const float4*>(
                                    src + (size_t)c0 * H_DIM) + lane);
        const float4 x1 = __ldg(reinterpret_cast<const float4*>(
                                    src + (size_t)c1 * H_DIM) + lane);
        const float4 x2 = __ldg(reinterpret_cast<const float4*>(
                                    src + (size_t)c2 * H_DIM) + lane);
        const float4 x3 = __ldg(reinterpret_cast<const float4*>(
                                    src + (size_t)c3 * H_DIM) + lane);

        float* p0 = dst + (size_t)r0 * H_DIM + lane * 4;
        float* p1 = dst + (size_t)r1 * H_DIM + lane * 4;
        float* p2 = dst + (size_t)r2 * H_DIM + lane * 4;
        float* p3 = dst + (size_t)r3 * H_DIM + lane * 4;
        asm volatile("red.global.add.v4.f32 [%0], {%1, %2, %3, %4};"
                     :: "l"(p0), "f"(x0.x * v0), "f"(x0.y * v0),
                        "f"(x0.z * v0), "f"(x0.w * v0) : "memory");
        asm volatile("red.global.add.v4.f32 [%0], {%1, %2, %3, %4};"
                     :: "l"(p1), "f"(x1.x * v1), "f"(x1.y * v1),
                        "f"(x1.z * v1), "f"(x1.w * v1) : "memory");
        asm volatile("red.global.add.v4.f32 [%0], {%1, %2, %3, %4};"
                     :: "l"(p2), "f"(x2.x * v2), "f"(x2.y * v2),
                        "f"(x2.z * v2), "f"(x2.w * v2) : "memory");
        asm volatile("red.global.add.v4.f32 [%0], {%1, %2, %3, %4};"
                     :: "l"(p3), "f"(x3.x * v3), "f"(x3.y * v3),
                        "f"(x3.z * v3), "f"(x3.w * v3) : "memory");
    }
}

// ---------------------------------------------------------------------------
// LayerNorm + exact-erf GELU, one warp per row
// ---------------------------------------------------------------------------
__global__ __launch_bounds__(256) void ln_gelu_kernel(const float* __restrict__ gamma,
                                                      const float* __restrict__ beta,
                                                      float* __restrict__ out) {
    const int warp = (blockIdx.x * blockDim.x + threadIdx.x) >> 5;
    const int lane = threadIdx.x & 31;
    if (warp >= N_NODES) return;

    const float* yrow = g_acc[2] + (size_t)warp * H_DIM;
    const float4 v = *reinterpret_cast<const float4*>(yrow + lane * 4);

    float s  = v.x + v.y + v.z + v.w;
    float sq = v.x * v.x + v.y * v.y + v.z * v.z + v.w * v.w;
#pragma unroll
    for (int o = 16; o; o >>= 1) {
        s  += __shfl_xor_sync(0xFFFFFFFFu, s,  o);
        sq += __shfl_xor_sync(0xFFFFFFFFu, sq, o);
    }
    const float mean = s * (1.f / H_DIM);
    const float var  = sq * (1.f / H_DIM) - mean * mean;
    const float rstd = rsqrtf(var + LN_EPS);

    const float4 g = *reinterpret_cast<const float4*>(gamma + lane * 4);
    const float4 b = *reinterpret_cast<const float4*>(beta  + lane * 4);

    auto gelu = [](float t) {
        return 0.5f * t * (1.f + erff(t * 0.7071067811865476f));
    };
    float4 r;
    r.x = gelu((v.x - mean) * rstd * g.x + b.x);
    r.y = gelu((v.y - mean) * rstd * g.y + b.y);
    r.z = gelu((v.z - mean) * rstd * g.z + b.z);
    r.w = gelu((v.w - mean) * rstd * g.w + b.w);

    *reinterpret_cast<float4*>(out + (size_t)warp * H_DIM + lane * 4) = r;
}

// ---------------------------------------------------------------------------
// kernel_launch
// inputs: x, adj_rows, adj_cols, adj_vals, idxes_seq, idxes_res,
//         W, b, gamma, beta
// ---------------------------------------------------------------------------
extern "C" void kernel_launch(void* const* d_in, const int* in_sizes, int n_in,
                              void* d_out, int out_size) {
    const float* x        = (const float*)d_in[0];
    const int*   adj_rows = (const int*)  d_in[1];
    const int*   adj_cols = (const int*)  d_in[2];
    const float* adj_vals = (const float*)d_in[3];
    const int*   idx_seq  = (const int*)  d_in[4];
    const int*   idx_res  = (const int*)  d_in[5];
    const float* W        = (const float*)d_in[6];
    const float* b        = (const float*)d_in[7];
    const float* gamma    = (const float*)d_in[8];
    const float* beta     = (const float*)d_in[9];
    float*       out      = (float*)d_out;

    zero_kernel<<<1024, 256>>>();
    zip_kernel<<<(N_ADJ * NNZ_C + 255) / 256, 256>>>(adj_cols, adj_vals);
    gemm_kernel<<<(N_NODES + 127) / 128, 256>>>(x, W, b);

    const int SPMM_GRID = (NNZ_C / 32 * 32 + 255) / 256;   // 25000 warps
    // state ids: 0 = s0 (g_h), 1 = s1, 2 = s2, 3 = s3
    // s1 = A[seq0] @ s0
    spmm_kernel<<<SPMM_GRID, 256>>>(adj_rows, idx_seq + 0, 0, 1);
    // s2 = A[seq1] @ s1 + A[res0] @ s0
    spmm_kernel<<<SPMM_GRID, 256>>>(adj_rows, idx_seq + 1, 1, 2);
    spmm_kernel<<<SPMM_GRID, 256>>>(adj_rows, idx_res + 0, 0, 2);
    // s3 = A[seq2] @ s2 + A[res1] @ s0 + A[res2] @ s1
    spmm_kernel<<<SPMM_GRID, 256>>>(adj_rows, idx_seq + 2, 2, 3);
    spmm_kernel<<<SPMM_GRID, 256>>>(adj_rows, idx_res + 1, 0, 3);
    spmm_kernel<<<SPMM_GRID, 256>>>(adj_rows, idx_res + 2, 1, 3);

    ln_gelu_kernel<<<(N_NODES * 32 + 255) / 256, 256>>>(gamma, beta, out);
}

// round 8
// speedup vs baseline: 1.0276x; 1.0276x over previous
#include <cuda_runtime.h>
#include <cuda_fp16.h>
#include <cstdint>

#define N_NODES 50000
#define NNZ_C   800000
#define N_ADJ   6
#define K_DIM   256
#define H_DIM   128
#define LN_EPS  1e-5f

// ---------------------------------------------------------------------------
// Device-global scratch
//   g_half[0..2] : fp16 gather sources for s0, s1, s2
//   g_acc [0..2] : fp32 RED accumulators for s1, s2, s3
// ---------------------------------------------------------------------------
__device__ __half g_half[3][(size_t)N_NODES * H_DIM];
__device__ float  g_acc[3][(size_t)N_NODES * H_DIM];
__device__ int2   g_ecv[N_ADJ][NNZ_C];                 // zipped (col, val bits)

// ---------------------------------------------------------------------------
// Zero the fp32 accumulators each call
// ---------------------------------------------------------------------------
__global__ void zero_kernel() {
    const size_t n4 = (size_t)3 * N_NODES * H_DIM / 4;
    float4* p = reinterpret_cast<float4*>(&g_acc[0][0]);
    const float4 z = make_float4(0.f, 0.f, 0.f, 0.f);
    for (size_t i = (size_t)blockIdx.x * blockDim.x + threadIdx.x; i < n4;
         i += (size_t)gridDim.x * blockDim.x)
        p[i] = z;
}

// ---------------------------------------------------------------------------
// Zip cols+vals into int2 (streaming)
// ---------------------------------------------------------------------------
__global__ __launch_bounds__(256) void zip_kernel(const int*   __restrict__ cols_base,
                                                  const float* __restrict__ vals_base) {
    const size_t i = (size_t)blockIdx.x * blockDim.x + threadIdx.x;
    if (i < (size_t)N_ADJ * NNZ_C)
        (&g_ecv[0][0])[i] = make_int2(__ldg(cols_base + i),
                                      __float_as_int(__ldg(vals_base + i)));
}

// ---------------------------------------------------------------------------
// Convert fp32 accumulator sid (s1 or s2) into fp16 mirror sid+1
// Each thread converts 4 floats -> 4 halves (8B store).
// ---------------------------------------------------------------------------
__global__ __launch_bounds__(256) void tohalf_kernel(int sid) {
    const size_t i = (size_t)blockIdx.x * blockDim.x + threadIdx.x;
    const size_t n4 = (size_t)N_NODES * H_DIM / 4;
    if (i >= n4) return;
    const float4 v = reinterpret_cast<const float4*>(&g_acc[sid][0])[i];
    __half2 h0 = __floats2half2_rn(v.x, v.y);
    __half2 h1 = __floats2half2_rn(v.z, v.w);
    uint2 pk;
    pk.x = *reinterpret_cast<const unsigned int*>(&h0);
    pk.y = *reinterpret_cast<const unsigned int*>(&h1);
    reinterpret_cast<uint2*>(&g_half[sid + 1][0])[i] = pk;
}

// ---------------------------------------------------------------------------
// GEMM: g_half[0] = fp16(X[50000,256] @ W[256,128] + b)
// ---------------------------------------------------------------------------
__global__ __launch_bounds__(256) void gemm_kernel(const float* __restrict__ X,
                                                   const float* __restrict__ W,
                                                   const float* __restrict__ bias) {
    __shared__ float As[8][128];
    __shared__ float Bs[8][128];

    const int tid = threadIdx.x;
    const int tx = tid & 15;
    const int ty = tid >> 4;
    const int row0 = blockIdx.x * 128;

    const int arow = tid >> 1;
    const int ak   = (tid & 1) * 4;
    const int grow = min(row0 + arow, N_NODES - 1);
    const int brow = tid >> 5;
    const int bcol = (tid & 31) * 4;

    float acc[8][8];
#pragma unroll
    for (int i = 0; i < 8; i++)
#pragma unroll
        for (int j = 0; j < 8; j++) acc[i][j] = 0.f;

    for (int k0 = 0; k0 < K_DIM; k0 += 8) {
        const float4 av = *reinterpret_cast<const float4*>(
            X + (size_t)grow * K_DIM + k0 + ak);
        const float4 bv = *reinterpret_cast<const float4*>(
            W + (size_t)(k0 + brow) * H_DIM + bcol);
        __syncthreads();
        As[ak + 0][arow] = av.x;
        As[ak + 1][arow] = av.y;
        As[ak + 2][arow] = av.z;
        As[ak + 3][arow] = av.w;
        *reinterpret_cast<float4*>(&Bs[brow][bcol]) = bv;
        __syncthreads();

#pragma unroll
        for (int kk = 0; kk < 8; kk++) {
            float a[8], b[8];
            const float4 a0 = *reinterpret_cast<const float4*>(&As[kk][ty * 8]);
            const float4 a1 = *reinterpret_cast<const float4*>(&As[kk][ty * 8 + 4]);
            const float4 b0 = *reinterpret_cast<const float4*>(&Bs[kk][tx * 8]);
            const float4 b1 = *reinterpret_cast<const float4*>(&Bs[kk][tx * 8 + 4]);
            a[0]=a0.x; a[1]=a0.y; a[2]=a0.z; a[3]=a0.w;
            a[4]=a1.x; a[5]=a1.y; a[6]=a1.z; a[7]=a1.w;
            b[0]=b0.x; b[1]=b0.y; b[2]=b0.z; b[3]=b0.w;
            b[4]=b1.x; b[5]=b1.y; b[6]=b1.z; b[7]=b1.w;
#pragma unroll
            for (int i = 0; i < 8; i++)
#pragma unroll
                for (int j = 0; j < 8; j++) acc[i][j] += a[i] * b[j];
        }
    }

    const int colb = tx * 8;
    const float4 bia0 = *reinterpret_cast<const float4*>(bias + colb);
    const float4 bia1 = *reinterpret_cast<const float4*>(bias + colb + 4);
#pragma unroll
    for (int i = 0; i < 8; i++) {
        const int row = row0 + ty * 8 + i;
        if (row < N_NODES) {
            __half2 p0 = __floats2half2_rn(acc[i][0] + bia0.x, acc[i][1] + bia0.y);
            __half2 p1 = __floats2half2_rn(acc[i][2] + bia0.z, acc[i][3] + bia0.w);
            __half2 p2 = __floats2half2_rn(acc[i][4] + bia1.x, acc[i][5] + bia1.y);
            __half2 p3 = __floats2half2_rn(acc[i][6] + bia1.z, acc[i][7] + bia1.w);
            uint4 pk;
            pk.x = *reinterpret_cast<const unsigned int*>(&p0);
            pk.y = *reinterpret_cast<const unsigned int*>(&p1);
            pk.z = *reinterpret_cast<const unsigned int*>(&p2);
            pk.w = *reinterpret_cast<const unsigned int*>(&p3);
            *reinterpret_cast<uint4*>(&g_half[0][(size_t)row * H_DIM + colb]) = pk;
        }
    }
}

// ---------------------------------------------------------------------------
// SpMM (COO + RED), fp16 gather source, fp32 RED target.
// One warp per 32-edge chunk; lane-cooperative metadata + shfl broadcast.
// Per edge: 256B gather (uint2/lane) + 512B RED.
// ---------------------------------------------------------------------------
__global__ __launch_bounds__(256) void spmm_kernel(const int* __restrict__ rows_base,
                                                   const int* __restrict__ idxp,
                                                   int src_id, int dst_id) {
    const int lane  = threadIdx.x & 31;
    const int chunk = (blockIdx.x * blockDim.x + threadIdx.x) >> 5;
    if (chunk >= NNZ_C / 32) return;

    const int a = __ldg(idxp);
    const __half* __restrict__ src = g_half[src_id];
    float*        __restrict__ dst = g_acc[dst_id];

    const size_t e0 = (size_t)chunk * 32;
    const int  myrow = __ldg(rows_base + (size_t)a * NNZ_C + e0 + lane);
    const int2 mycv  = __ldg(&g_ecv[a][e0 + lane]);

#pragma unroll
    for (int j = 0; j < 32; j++) {
        const int   row = __shfl_sync(0xFFFFFFFFu, myrow, j);
        const int   col = __shfl_sync(0xFFFFFFFFu, mycv.x, j);
        const float val = __int_as_float(__shfl_sync(0xFFFFFFFFu, mycv.y, j));

        const uint2 hv = __ldg(reinterpret_cast<const uint2*>(
                                   src + (size_t)col * H_DIM) + lane);
        const float2 f01 = __half22float2(*reinterpret_cast<const __half2*>(&hv.x));
        const float2 f23 = __half22float2(*reinterpret_cast<const __half2*>(&hv.y));

        float* p = dst + (size_t)row * H_DIM + lane * 4;
        asm volatile("red.global.add.v4.f32 [%0], {%1, %2, %3, %4};"
                     :: "l"(p), "f"(f01.x * val), "f"(f01.y * val),
                        "f"(f23.x * val), "f"(f23.y * val)
                     : "memory");
    }
}

// ---------------------------------------------------------------------------
// LayerNorm + exact-erf GELU, one warp per row (reads fp32 s3)
// ---------------------------------------------------------------------------
__global__ __launch_bounds__(256) void ln_gelu_kernel(const float* __restrict__ gamma,
                                                      const float* __restrict__ beta,
                                                      float* __restrict__ out) {
    const int warp = (blockIdx.x * blockDim.x + threadIdx.x) >> 5;
    const int lane = threadIdx.x & 31;
    if (warp >= N_NODES) return;

    const float* yrow = g_acc[2] + (size_t)warp * H_DIM;
    const float4 v = *reinterpret_cast<const float4*>(yrow + lane * 4);

    float s  = v.x + v.y + v.z + v.w;
    float sq = v.x * v.x + v.y * v.y + v.z * v.z + v.w * v.w;
#pragma unroll
    for (int o = 16; o; o >>= 1) {
        s  += __shfl_xor_sync(0xFFFFFFFFu, s,  o);
        sq += __shfl_xor_sync(0xFFFFFFFFu, sq, o);
    }
    const float mean = s * (1.f / H_DIM);
    const float var  = sq * (1.f / H_DIM) - mean * mean;
    const float rstd = rsqrtf(var + LN_EPS);

    const float4 g = *reinterpret_cast<const float4*>(gamma + lane * 4);
    const float4 b = *reinterpret_cast<const float4*>(beta  + lane * 4);

    auto gelu = [](float t) {
        return 0.5f * t * (1.f + erff(t * 0.7071067811865476f));
    };
    float4 r;
    r.x = gelu((v.x - mean) * rstd * g.x + b.x);
    r.y = gelu((v.y - mean) * rstd * g.y + b.y);
    r.z = gelu((v.z - mean) * rstd * g.z + b.z);
    r.w = gelu((v.w - mean) * rstd * g.w + b.w);

    *reinterpret_cast<float4*>(out + (size_t)warp * H_DIM + lane * 4) = r;
}

// ---------------------------------------------------------------------------
// kernel_launch
// inputs: x, adj_rows, adj_cols, adj_vals, idxes_seq, idxes_res,
//         W, b, gamma, beta
// ---------------------------------------------------------------------------
extern "C" void kernel_launch(void* const* d_in, const int* in_sizes, int n_in,
                              void* d_out, int out_size) {
    const float* x        = (const float*)d_in[0];
    const int*   adj_rows = (const int*)  d_in[1];
    const int*   adj_cols = (const int*)  d_in[2];
    const float* adj_vals = (const float*)d_in[3];
    const int*   idx_seq  = (const int*)  d_in[4];
    const int*   idx_res  = (const int*)  d_in[5];
    const float* W        = (const float*)d_in[6];
    const float* b        = (const float*)d_in[7];
    const float* gamma    = (const float*)d_in[8];
    const float* beta     = (const float*)d_in[9];
    float*       out      = (float*)d_out;

    zero_kernel<<<1024, 256>>>();
    zip_kernel<<<(N_ADJ * NNZ_C + 255) / 256, 256>>>(adj_cols, adj_vals);
    gemm_kernel<<<(N_NODES + 127) / 128, 256>>>(x, W, b);   // -> g_half[0]

    const int SPMM_GRID = (NNZ_C / 32 * 32 + 255) / 256;    // 25000 warps
    const int CVT_GRID  = (N_NODES * H_DIM / 4 + 255) / 256;

    // s1 (acc0) = A[seq0] @ h0
    spmm_kernel<<<SPMM_GRID, 256>>>(adj_rows, idx_seq + 0, 0, 0);
    tohalf_kernel<<<CVT_GRID, 256>>>(0);                    // h1 = fp16(s1)
    // s2 (acc1) = A[seq1] @ h1 + A[res0] @ h0
    spmm_kernel<<<SPMM_GRID, 256>>>(adj_rows, idx_seq + 1, 1, 1);
    spmm_kernel<<<SPMM_GRID, 256>>>(adj_rows, idx_res + 0, 0, 1);
    tohalf_kernel<<<CVT_GRID, 256>>>(1);                    // h2 = fp16(s2)
    // s3 (acc2) = A[seq2] @ h2 + A[res1] @ h0 + A[res2] @ h1
    spmm_kernel<<<SPMM_GRID, 256>>>(adj_rows, idx_seq + 2, 2, 2);
    spmm_kernel<<<SPMM_GRID, 256>>>(adj_rows, idx_res + 1, 0, 2);
    spmm_kernel<<<SPMM_GRID, 256>>>(adj_rows, idx_res + 2, 1, 2);

    ln_gelu_kernel<<<(N_NODES * 32 + 255) / 256, 256>>>(gamma, beta, out);
}